// round 13
// baseline (speedup 1.0000x reference)
#include <cuda_runtime.h>
#include <cuda_fp16.h>
#include <cstdint>

#define TOK 8192
#define HD  2048
#define ID  1408
#define NE  8

#define BM   64
#define BK   64
#define BN1  64
#define BN2  128
#define NTHR 128
#define KT1  (HD / BK)    // 32
#define KT2  (ID / BK)    // 22
#define A_ST 72           // 64 + 8 halves -> 144B row stride
#define B1_ST 72          // [k][n], n=64
#define B2_ST 136         // [k][n], n=128

// ---------------- device scratch (no allocations allowed) ----------------------
__device__ __half g_xh[(size_t)TOK * HD];       // fp16 x
__device__ __half g_wgh[(size_t)NE * HD * ID];  // fp16 weights, native [k][n]
__device__ __half g_wuh[(size_t)NE * HD * ID];
__device__ __half g_wdh[(size_t)NE * ID * HD];
__device__ int    g_cnt[NE];
__device__ int    g_tokp[NE * TOK];             // token | (k<<31)
__device__ float  g_w2[TOK * 2];                // per-token (w0, w1)
__device__ __half g_hh[(size_t)NE * TOK * ID];  // fp16 intermediate (slot-indexed)
__device__ float  g_y[(size_t)2 * TOK * HD];    // unweighted expert outputs per k

// ---------------- helpers ------------------------------------------------------
__device__ __forceinline__ uint32_t saddr(const void* p) {
    return (uint32_t)__cvta_generic_to_shared(p);
}
__device__ __forceinline__ void cp16(uint32_t dst, const void* src) {
    asm volatile("cp.async.cg.shared.global [%0], [%1], 16;" :: "r"(dst), "l"(src));
}
__device__ __forceinline__ void cp_commit() { asm volatile("cp.async.commit_group;"); }
template <int N>
__device__ __forceinline__ void cp_wait() { asm volatile("cp.async.wait_group %0;" :: "n"(N)); }

__device__ __forceinline__ void ldsm_x4(uint32_t* r, uint32_t addr) {
    asm volatile("ldmatrix.sync.aligned.m8n8.x4.shared.b16 {%0,%1,%2,%3}, [%4];"
                 : "=r"(r[0]), "=r"(r[1]), "=r"(r[2]), "=r"(r[3]) : "r"(addr));
}
__device__ __forceinline__ void ldsm_x4t(uint32_t* r, uint32_t addr) {
    asm volatile("ldmatrix.sync.aligned.m8n8.x4.trans.shared.b16 {%0,%1,%2,%3}, [%4];"
                 : "=r"(r[0]), "=r"(r[1]), "=r"(r[2]), "=r"(r[3]) : "r"(addr));
}
__device__ __forceinline__ void mma_f16(float d[4], const uint32_t a[4], const uint32_t b[2]) {
    asm volatile(
        "mma.sync.aligned.m16n8k16.row.col.f32.f16.f16.f32 "
        "{%0,%1,%2,%3}, {%4,%5,%6,%7}, {%8,%9}, {%0,%1,%2,%3};"
        : "+f"(d[0]), "+f"(d[1]), "+f"(d[2]), "+f"(d[3])
        : "r"(a[0]), "r"(a[1]), "r"(a[2]), "r"(a[3]), "r"(b[0]), "r"(b[1]));
}

// ---------------- small kernels ------------------------------------------------
__global__ void zero_cnt_kernel() {
    if (threadIdx.x < NE) g_cnt[threadIdx.x] = 0;
}

__global__ void conv_half_kernel(const float4* __restrict__ wg,
                                 const float4* __restrict__ wu,
                                 const float4* __restrict__ wd) {
    const int n4 = NE * HD * ID / 4;
    const float4* in = blockIdx.z == 0 ? wg : blockIdx.z == 1 ? wu : wd;
    uint2* out = (uint2*)(blockIdx.z == 0 ? g_wgh : blockIdx.z == 1 ? g_wuh : g_wdh);
    for (int i = blockIdx.x * blockDim.x + threadIdx.x; i < n4; i += gridDim.x * blockDim.x) {
        float4 v = in[i];
        __half2 lo = __floats2half2_rn(v.x, v.y);
        __half2 hi = __floats2half2_rn(v.z, v.w);
        uint2 o;
        o.x = *(uint32_t*)&lo;
        o.y = *(uint32_t*)&hi;
        out[i] = o;
    }
}

// Router + fused fp16 conversion of x. One warp per token.
__global__ void router_kernel(const float* __restrict__ x, const float* __restrict__ gw) {
    extern __shared__ float s_gw[];  // NE*HD = 64 KB
    for (int i = threadIdx.x; i < NE * HD; i += blockDim.x) s_gw[i] = gw[i];
    __syncthreads();

    int gtid = blockIdx.x * blockDim.x + threadIdx.x;
    int t = gtid >> 5, lane = gtid & 31;
    if (t >= TOK) return;

    float acc[NE];
#pragma unroll
    for (int e = 0; e < NE; e++) acc[e] = 0.f;

    const float* xr = x + (size_t)t * HD;
    __half* xo = g_xh + (size_t)t * HD;
    for (int i = lane; i < HD; i += 32) {
        float xv = xr[i];
        xo[i] = __float2half_rn(xv);
#pragma unroll
        for (int e = 0; e < NE; e++) acc[e] += xv * s_gw[e * HD + i];
    }
#pragma unroll
    for (int e = 0; e < NE; e++) {
#pragma unroll
        for (int off = 16; off > 0; off >>= 1)
            acc[e] += __shfl_xor_sync(0xffffffffu, acc[e], off);
    }
    if (lane == 0) {
        int i0 = 0; float l0 = acc[0];
#pragma unroll
        for (int e = 1; e < NE; e++) if (acc[e] > l0) { l0 = acc[e]; i0 = e; }
        int i1 = -1; float l1 = -1e30f;
#pragma unroll
        for (int e = 0; e < NE; e++) if (e != i0 && acc[e] > l1) { l1 = acc[e]; i1 = e; }
        float ex = __expf(l1 - l0);
        float w0 = 1.f / (1.f + ex);
        float w1 = ex * w0;
        g_w2[2 * t] = w0;
        g_w2[2 * t + 1] = w1;
        int s0 = atomicAdd(&g_cnt[i0], 1);
        g_tokp[i0 * TOK + s0] = t;                          // k = 0
        int s1 = atomicAdd(&g_cnt[i1], 1);
        g_tokp[i1 * TOK + s1] = t | 0x80000000;             // k = 1
    }
}

// ---------------- GEMM1: h = silu(x@Wg)*(x@Wu); 64x64x64, 4 CTAs/SM -------------
// 4 warps as 2(m) x 2(n); warp tile 32x32 for BOTH g and u -> 64 acc regs.
// One warp per SMSP; 4 CTAs/SM give each SMSP 4 independent warps.
struct SmemG1 {
    __half A[2][BM][A_ST];      // 18432 B
    __half Bg[2][BK][B1_ST];    // 18432 B
    __half Bu[2][BK][B1_ST];    // 18432 B
    int    tok[BM];             // 256 B
};                              // ~55.5 KB -> 4 CTAs/SM

__device__ __forceinline__ void g1_load(SmemG1* s, int st, int k0,
                                        int e, int n_base, int tid) {
#pragma unroll
    for (int i = 0; i < 4; i++) {                 // A: 64 rows x 8 chunks = 512
        int idx = tid + i * NTHR;
        int row = idx >> 3, c = idx & 7;
        cp16(saddr(&s->A[st][row][c * 8]),
             &g_xh[(size_t)s->tok[row] * HD + k0 + c * 8]);
    }
    const __half* bg = g_wgh + ((size_t)e * HD + k0) * ID + n_base;
    const __half* bu = g_wuh + ((size_t)e * HD + k0) * ID + n_base;
#pragma unroll
    for (int i = 0; i < 4; i++) {                 // Bg/Bu: 64 k-rows x 8 chunks
        int idx = tid + i * NTHR;
        int kr = idx >> 3, c = idx & 7;
        cp16(saddr(&s->Bg[st][kr][c * 8]), bg + (size_t)kr * ID + c * 8);
        cp16(saddr(&s->Bu[st][kr][c * 8]), bu + (size_t)kr * ID + c * 8);
    }
}

__global__ void __launch_bounds__(NTHR, 4) gemm1_kernel() {
    extern __shared__ __align__(16) char smem_raw[];
    SmemG1* s = (SmemG1*)smem_raw;

    int e = blockIdx.z;
    int cnt = g_cnt[e];
    int m_base = blockIdx.y * BM;
    if (m_base >= cnt) return;
    int n_base = blockIdx.x * BN1;
    int tid = threadIdx.x;

    if (tid < BM) {
        int m = m_base + tid;
        s->tok[tid] = (m < cnt) ? (g_tokp[e * TOK + m] & 0x7fffffff) : 0;
    }
    __syncthreads();

    int wid = tid >> 5, lane = tid & 31;
    int wm = wid >> 1, wn = wid & 1;               // 2 x 2 warps, warp 32x32
    int r = lane >> 2, cq = lane & 3;
    int lrow = lane & 15, lcol = (lane >> 4) << 3;

    float acc_g[2][4][4], acc_u[2][4][4];
#pragma unroll
    for (int mf = 0; mf < 2; mf++)
#pragma unroll
        for (int nf = 0; nf < 4; nf++)
#pragma unroll
            for (int k = 0; k < 4; k++) { acc_g[mf][nf][k] = 0.f; acc_u[mf][nf][k] = 0.f; }

    g1_load(s, 0, 0, e, n_base, tid);
    cp_commit();

    for (int kt = 0; kt < KT1; kt++) {
        if (kt + 1 < KT1) {
            g1_load(s, (kt + 1) & 1, (kt + 1) * BK, e, n_base, tid);
            cp_commit();
            cp_wait<1>();
        } else {
            cp_wait<0>();
        }
        __syncthreads();

        int sg = kt & 1;
        uint32_t sA  = saddr(&s->A[sg][0][0]);
        uint32_t sBg = saddr(&s->Bg[sg][0][0]);
        uint32_t sBu = saddr(&s->Bu[sg][0][0]);
#pragma unroll
        for (int ks = 0; ks < BK / 16; ks++) {
            int k16 = ks * 16;
            uint32_t a[2][4];
#pragma unroll
            for (int mf = 0; mf < 2; mf++)
                ldsm_x4(a[mf], sA + 2 * ((wm * 32 + mf * 16 + lrow) * A_ST + k16 + lcol));
            uint32_t bg[2][4], bu[2][4];
#pragma unroll
            for (int ng = 0; ng < 2; ng++) {
                uint32_t off = 2 * ((k16 + lrow) * B1_ST + wn * 32 + ng * 16 + lcol);
                ldsm_x4t(bg[ng], sBg + off);
                ldsm_x4t(bu[ng], sBu + off);
            }
#pragma unroll
            for (int mf = 0; mf < 2; mf++)
#pragma unroll
                for (int nf = 0; nf < 4; nf++) {
                    mma_f16(acc_g[mf][nf], a[mf], &bg[nf >> 1][(nf & 1) * 2]);
                    mma_f16(acc_u[mf][nf], a[mf], &bu[nf >> 1][(nf & 1) * 2]);
                }
        }
        __syncthreads();
    }

    // epilogue: silu(g)*u -> fp16 -> g_hh
#pragma unroll
    for (int mf = 0; mf < 2; mf++) {
#pragma unroll
        for (int nf = 0; nf < 4; nf++) {
            int rl = wm * 32 + mf * 16 + r;
            int col = n_base + wn * 32 + nf * 8 + cq * 2;
            if (m_base + rl < cnt) {
                float g0 = acc_g[mf][nf][0], u0 = acc_u[mf][nf][0];
                float g1 = acc_g[mf][nf][1], u1 = acc_u[mf][nf][1];
                float v0 = (g0 / (1.f + __expf(-g0))) * u0;
                float v1 = (g1 / (1.f + __expf(-g1))) * u1;
                __half2* p = (__half2*)&g_hh[((size_t)e * TOK + m_base + rl) * ID + col];
                *p = __floats2half2_rn(v0, v1);
            }
            if (m_base + rl + 8 < cnt) {
                float g0 = acc_g[mf][nf][2], u0 = acc_u[mf][nf][2];
                float g1 = acc_g[mf][nf][3], u1 = acc_u[mf][nf][3];
                float v0 = (g0 / (1.f + __expf(-g0))) * u0;
                float v1 = (g1 / (1.f + __expf(-g1))) * u1;
                __half2* p = (__half2*)&g_hh[((size_t)e * TOK + m_base + rl + 8) * ID + col];
                *p = __floats2half2_rn(v0, v1);
            }
        }
    }
}

// ---------------- GEMM2: y = h @ Wd; 64x128x64, 4 CTAs/SM -----------------------
// 4 warps as 2(m) x 2(n); warp tile 32x64 -> 64 acc regs.
struct SmemG2 {
    __half A[2][BM][A_ST];      // 18432 B
    __half B[2][BK][B2_ST];     // 34816 B
};                              // ~53.2 KB -> 4 CTAs/SM

__device__ __forceinline__ void g2_load(SmemG2* s, int st, int k0,
                                        int e, int m_base, int n_base, int tid) {
    const __half* arow = g_hh + ((size_t)e * TOK + m_base) * ID + k0;
    const __half* brow = g_wdh + ((size_t)e * ID + k0) * HD + n_base;
#pragma unroll
    for (int i = 0; i < 4; i++) {                 // A: 512 chunks
        int idx = tid + i * NTHR;
        int row = idx >> 3, c = idx & 7;
        cp16(saddr(&s->A[st][row][c * 8]), arow + (size_t)row * ID + c * 8);
    }
#pragma unroll
    for (int i = 0; i < 8; i++) {                 // B: 64 k-rows x 16 chunks = 1024
        int idx = tid + i * NTHR;
        int kr = idx >> 4, c = idx & 15;
        cp16(saddr(&s->B[st][kr][c * 8]), brow + (size_t)kr * HD + c * 8);
    }
}

__global__ void __launch_bounds__(NTHR, 4) gemm2_kernel() {
    extern __shared__ __align__(16) char smem_raw[];
    SmemG2* s = (SmemG2*)smem_raw;

    int e = blockIdx.z;
    int cnt = g_cnt[e];
    int m_base = blockIdx.y * BM;
    if (m_base >= cnt) return;
    int n_base = blockIdx.x * BN2;
    int tid = threadIdx.x;

    int wid = tid >> 5, lane = tid & 31;
    int wm = wid >> 1, wn = wid & 1;               // 2 x 2 warps, warp 32x64
    int r = lane >> 2, cq = lane & 3;
    int lrow = lane & 15, lcol = (lane >> 4) << 3;

    float acc[2][8][4];
#pragma unroll
    for (int mf = 0; mf < 2; mf++)
#pragma unroll
        for (int nf = 0; nf < 8; nf++)
#pragma unroll
            for (int k = 0; k < 4; k++) acc[mf][nf][k] = 0.f;

    g2_load(s, 0, 0, e, m_base, n_base, tid);
    cp_commit();

    for (int kt = 0; kt < KT2; kt++) {
        if (kt + 1 < KT2) {
            g2_load(s, (kt + 1) & 1, (kt + 1) * BK, e, m_base, n_base, tid);
            cp_commit();
            cp_wait<1>();
        } else {
            cp_wait<0>();
        }
        __syncthreads();

        int sg = kt & 1;
        uint32_t sA = saddr(&s->A[sg][0][0]);
        uint32_t sB = saddr(&s->B[sg][0][0]);
#pragma unroll
        for (int ks = 0; ks < BK / 16; ks++) {
            int k16 = ks * 16;
            uint32_t a[2][4];
#pragma unroll
            for (int mf = 0; mf < 2; mf++)
                ldsm_x4(a[mf], sA + 2 * ((wm * 32 + mf * 16 + lrow) * A_ST + k16 + lcol));
            uint32_t b[4][4];
#pragma unroll
            for (int ng = 0; ng < 4; ng++) {
                uint32_t off = 2 * ((k16 + lrow) * B2_ST + wn * 64 + ng * 16 + lcol);
                ldsm_x4t(b[ng], sB + off);
            }
#pragma unroll
            for (int mf = 0; mf < 2; mf++)
#pragma unroll
                for (int nf = 0; nf < 8; nf++)
                    mma_f16(acc[mf][nf], a[mf], &b[nf >> 1][(nf & 1) * 2]);
        }
        __syncthreads();
    }

    // epilogue: plain stores to g_y[k][t]
#pragma unroll
    for (int mf = 0; mf < 2; mf++) {
        int rl0 = wm * 32 + mf * 16 + r;
        int pk0 = (m_base + rl0 < cnt) ? g_tokp[e * TOK + m_base + rl0] : -1;
        int pk1 = (m_base + rl0 + 8 < cnt) ? g_tokp[e * TOK + m_base + rl0 + 8] : -1;
#pragma unroll
        for (int nf = 0; nf < 8; nf++) {
            int col = n_base + wn * 64 + nf * 8 + cq * 2;
            if (pk0 != -1) {
                int t = pk0 & 0x7fffffff;
                int k = (uint32_t)pk0 >> 31;
                float2* p = (float2*)&g_y[((size_t)k * TOK + t) * HD + col];
                *p = make_float2(acc[mf][nf][0], acc[mf][nf][1]);
            }
            if (pk1 != -1) {
                int t = pk1 & 0x7fffffff;
                int k = (uint32_t)pk1 >> 31;
                float2* p = (float2*)&g_y[((size_t)k * TOK + t) * HD + col];
                *p = make_float2(acc[mf][nf][2], acc[mf][nf][3]);
            }
        }
    }
}

// ---------------- combine: out = w0*y0 + w1*y1 ----------------------------------
__global__ void combine_kernel(float4* __restrict__ out) {
    const int n4 = TOK * HD / 4;
    const float4* y0 = (const float4*)g_y;
    const float4* y1 = y0 + n4;
    for (int i = blockIdx.x * blockDim.x + threadIdx.x; i < n4; i += gridDim.x * blockDim.x) {
        int t = i / (HD / 4);
        float w0 = g_w2[2 * t], w1 = g_w2[2 * t + 1];
        float4 a = y0[i], b = y1[i];
        float4 o;
        o.x = w0 * a.x + w1 * b.x;
        o.y = w0 * a.y + w1 * b.y;
        o.z = w0 * a.z + w1 * b.z;
        o.w = w0 * a.w + w1 * b.w;
        out[i] = o;
    }
}

// ---------------- host launcher -------------------------------------------------
extern "C" void kernel_launch(void* const* d_in, const int* in_sizes, int n_in,
                              void* d_out, int out_size) {
    const float* x  = (const float*)d_in[0];
    const float* gw = (const float*)d_in[1];
    const float* wg = (const float*)d_in[2];
    const float* wu = (const float*)d_in[3];
    const float* wd = (const float*)d_in[4];
    (void)in_sizes; (void)n_in; (void)out_size;

    zero_cnt_kernel<<<1, 32>>>();

    {
        dim3 grid(1024, 1, 3);
        conv_half_kernel<<<grid, 256>>>((const float4*)wg, (const float4*)wu,
                                        (const float4*)wd);
    }

    cudaFuncSetAttribute(router_kernel, cudaFuncAttributeMaxDynamicSharedMemorySize,
                         NE * HD * (int)sizeof(float));
    router_kernel<<<TOK * 32 / 256, 256, NE * HD * sizeof(float)>>>(x, gw);

    cudaFuncSetAttribute(gemm1_kernel, cudaFuncAttributeMaxDynamicSharedMemorySize,
                         (int)sizeof(SmemG1));
    dim3 grid1(ID / BN1, TOK / BM, NE);     // 22 x 128 x 8
    gemm1_kernel<<<grid1, NTHR, sizeof(SmemG1)>>>();

    cudaFuncSetAttribute(gemm2_kernel, cudaFuncAttributeMaxDynamicSharedMemorySize,
                         (int)sizeof(SmemG2));
    dim3 grid2(HD / BN2, TOK / BM, NE);     // 16 x 128 x 8
    gemm2_kernel<<<grid2, NTHR, sizeof(SmemG2)>>>();

    combine_kernel<<<2048, 256>>>((float4*)d_out);
}

// round 14
// speedup vs baseline: 1.1099x; 1.1099x over previous
#include <cuda_runtime.h>
#include <cuda_fp16.h>
#include <cstdint>

#define TOK 8192
#define HD  2048
#define ID  1408
#define NE  8

#define BM   64
#define BK   64
#define BN1  64
#define BN2  128
#define NTHR 128
#define KT1  (HD / BK)    // 32
#define KT2  (ID / BK)    // 22

// swizzle for 128B rows, 16B units
#define SWZ(b) ((uint32_t)(b) ^ (((uint32_t)(b) >> 3) & 0x70u))

// ---------------- device scratch (no allocations allowed) ----------------------
__device__ __half g_xh[(size_t)TOK * HD];       // fp16 x
__device__ __half g_wgh[(size_t)NE * HD * ID];  // fp16 weights, native [k][n]
__device__ __half g_wuh[(size_t)NE * HD * ID];
__device__ __half g_wdT[(size_t)NE * HD * ID];  // fp16 wd TRANSPOSED [e][H][I] ([n][k])
__device__ int    g_cnt[NE];
__device__ int    g_tokp[NE * TOK];             // token | (k<<31)
__device__ float  g_w2[TOK * 2];                // per-token (w0, w1)
__device__ __half g_hh[(size_t)NE * TOK * ID];  // fp16 intermediate (slot-indexed)
__device__ float  g_y[(size_t)2 * TOK * HD];    // unweighted expert outputs per k

// ---------------- helpers ------------------------------------------------------
__device__ __forceinline__ uint32_t saddr(const void* p) {
    return (uint32_t)__cvta_generic_to_shared(p);
}
__device__ __forceinline__ void cp16(uint32_t dst, const void* src) {
    asm volatile("cp.async.cg.shared.global [%0], [%1], 16;" :: "r"(dst), "l"(src));
}
__device__ __forceinline__ void cp_commit() { asm volatile("cp.async.commit_group;"); }
template <int N>
__device__ __forceinline__ void cp_wait() { asm volatile("cp.async.wait_group %0;" :: "n"(N)); }

__device__ __forceinline__ void ldsm_x4(uint32_t* r, uint32_t addr) {
    asm volatile("ldmatrix.sync.aligned.m8n8.x4.shared.b16 {%0,%1,%2,%3}, [%4];"
                 : "=r"(r[0]), "=r"(r[1]), "=r"(r[2]), "=r"(r[3]) : "r"(addr));
}
__device__ __forceinline__ void ldsm_x4t(uint32_t* r, uint32_t addr) {
    asm volatile("ldmatrix.sync.aligned.m8n8.x4.trans.shared.b16 {%0,%1,%2,%3}, [%4];"
                 : "=r"(r[0]), "=r"(r[1]), "=r"(r[2]), "=r"(r[3]) : "r"(addr));
}
__device__ __forceinline__ void mma_f16(float d[4], const uint32_t a[4], const uint32_t b[2]) {
    asm volatile(
        "mma.sync.aligned.m16n8k16.row.col.f32.f16.f16.f32 "
        "{%0,%1,%2,%3}, {%4,%5,%6,%7}, {%8,%9}, {%0,%1,%2,%3};"
        : "+f"(d[0]), "+f"(d[1]), "+f"(d[2]), "+f"(d[3])
        : "r"(a[0]), "r"(a[1]), "r"(a[2]), "r"(a[3]), "r"(b[0]), "r"(b[1]));
}

// ---------------- small kernels ------------------------------------------------
// straight fp32->fp16 for wg, wu; also zeroes g_cnt from one block
__global__ void conv_half_kernel(const float4* __restrict__ wg,
                                 const float4* __restrict__ wu) {
    if (blockIdx.x == 0 && blockIdx.z == 0 && threadIdx.x < NE)
        g_cnt[threadIdx.x] = 0;
    const int n4 = NE * HD * ID / 4;
    const float4* in = blockIdx.z == 0 ? wg : wu;
    uint2* out = (uint2*)(blockIdx.z == 0 ? g_wgh : g_wuh);
    for (int i = blockIdx.x * blockDim.x + threadIdx.x; i < n4; i += gridDim.x * blockDim.x) {
        float4 v = in[i];
        __half2 lo = __floats2half2_rn(v.x, v.y);
        __half2 hi = __floats2half2_rn(v.z, v.w);
        uint2 o;
        o.x = *(uint32_t*)&lo;
        o.y = *(uint32_t*)&hi;
        out[i] = o;
    }
}

// wd [I][H] fp32 -> wdT [H][I] fp16 (32x32 tile transpose)
__global__ void convT_wd_kernel(const float* __restrict__ wd) {
    __shared__ float t[32][33];
    int e = blockIdx.z;
    const float* in = wd + (size_t)e * ID * HD;
    __half* out = g_wdT + (size_t)e * HD * ID;
    int r0 = blockIdx.y * 32;   // ID dim
    int c0 = blockIdx.x * 32;   // HD dim
    int tx = threadIdx.x, ty = threadIdx.y;
#pragma unroll
    for (int i = 0; i < 4; i++)
        t[ty + i * 8][tx] = in[(size_t)(r0 + ty + i * 8) * HD + c0 + tx];
    __syncthreads();
#pragma unroll
    for (int i = 0; i < 4; i++)
        out[(size_t)(c0 + ty + i * 8) * ID + r0 + tx] = __float2half_rn(t[tx][ty + i * 8]);
}

// Router + fused fp16 conversion of x. One warp per token.
__global__ void router_kernel(const float* __restrict__ x, const float* __restrict__ gw) {
    extern __shared__ float s_gw[];  // NE*HD = 64 KB
    for (int i = threadIdx.x; i < NE * HD; i += blockDim.x) s_gw[i] = gw[i];
    __syncthreads();

    int gtid = blockIdx.x * blockDim.x + threadIdx.x;
    int t = gtid >> 5, lane = gtid & 31;
    if (t >= TOK) return;

    float acc[NE];
#pragma unroll
    for (int e = 0; e < NE; e++) acc[e] = 0.f;

    const float* xr = x + (size_t)t * HD;
    __half* xo = g_xh + (size_t)t * HD;
    for (int i = lane; i < HD; i += 32) {
        float xv = xr[i];
        xo[i] = __float2half_rn(xv);
#pragma unroll
        for (int e = 0; e < NE; e++) acc[e] += xv * s_gw[e * HD + i];
    }
#pragma unroll
    for (int e = 0; e < NE; e++) {
#pragma unroll
        for (int off = 16; off > 0; off >>= 1)
            acc[e] += __shfl_xor_sync(0xffffffffu, acc[e], off);
    }
    if (lane == 0) {
        int i0 = 0; float l0 = acc[0];
#pragma unroll
        for (int e = 1; e < NE; e++) if (acc[e] > l0) { l0 = acc[e]; i0 = e; }
        int i1 = -1; float l1 = -1e30f;
#pragma unroll
        for (int e = 0; e < NE; e++) if (e != i0 && acc[e] > l1) { l1 = acc[e]; i1 = e; }
        float ex = __expf(l1 - l0);
        float w0 = 1.f / (1.f + ex);
        float w1 = ex * w0;
        g_w2[2 * t] = w0;
        g_w2[2 * t + 1] = w1;
        int s0 = atomicAdd(&g_cnt[i0], 1);
        g_tokp[i0 * TOK + s0] = t;                          // k = 0
        int s1 = atomicAdd(&g_cnt[i1], 1);
        g_tokp[i1 * TOK + s1] = t | 0x80000000;             // k = 1
    }
}

// ---------------- GEMM1: h = silu(x@Wg)*(x@Wu); 64x64x64, 3 CTAs/SM, swizzled ---
// smem byte offsets (stage = 8192 B tile of 64 rows x 128 B)
#define G1_A(s)  ((s) * 8192)
#define G1_BG(s) (24576 + (s) * 8192)
#define G1_BU(s) (49152 + (s) * 8192)
#define G1_TOK   73728
#define G1_SMEM  73984

__device__ __forceinline__ void g1_load(uint32_t sb, const int* tok_s, int st, int k0,
                                        int e, int n_base, int tid) {
#pragma unroll
    for (int i = 0; i < 4; i++) {                 // A: 64 rows x 8 chunks = 512
        int idx = tid + i * NTHR;
        int row = idx >> 3, c = idx & 7;
        cp16(sb + G1_A(st) + SWZ(row * 128 + c * 16),
             &g_xh[(size_t)tok_s[row] * HD + k0 + c * 8]);
    }
    const __half* bg = g_wgh + ((size_t)e * HD + k0) * ID + n_base;
    const __half* bu = g_wuh + ((size_t)e * HD + k0) * ID + n_base;
#pragma unroll
    for (int i = 0; i < 4; i++) {                 // Bg/Bu: 64 k-rows x 8 chunks
        int idx = tid + i * NTHR;
        int kr = idx >> 3, c = idx & 7;
        uint32_t sw = SWZ(kr * 128 + c * 16);
        cp16(sb + G1_BG(st) + sw, bg + (size_t)kr * ID + c * 8);
        cp16(sb + G1_BU(st) + sw, bu + (size_t)kr * ID + c * 8);
    }
}

__global__ void __launch_bounds__(NTHR, 3) gemm1_kernel() {
    extern __shared__ __align__(1024) char smem_raw[];
    uint32_t sb = saddr(smem_raw);
    int* tok_s = (int*)(smem_raw + G1_TOK);

    int e = blockIdx.z;
    int cnt = g_cnt[e];
    int m_base = blockIdx.y * BM;
    if (m_base >= cnt) return;
    int n_base = blockIdx.x * BN1;
    int tid = threadIdx.x;

    if (tid < BM) {
        int m = m_base + tid;
        tok_s[tid] = (m < cnt) ? (g_tokp[e * TOK + m] & 0x7fffffff) : 0;
    }
    __syncthreads();

    int wid = tid >> 5, lane = tid & 31;
    int wm = wid >> 1, wn = wid & 1;               // 2 x 2 warps, warp 32x32
    int r = lane >> 2, cq = lane & 3;
    int lrow = lane & 15, lcol = (lane >> 4) << 3;

    float acc_g[2][4][4], acc_u[2][4][4];
#pragma unroll
    for (int mf = 0; mf < 2; mf++)
#pragma unroll
        for (int nf = 0; nf < 4; nf++)
#pragma unroll
            for (int k = 0; k < 4; k++) { acc_g[mf][nf][k] = 0.f; acc_u[mf][nf][k] = 0.f; }

    g1_load(sb, tok_s, 0, 0, e, n_base, tid);  cp_commit();
    g1_load(sb, tok_s, 1, BK, e, n_base, tid); cp_commit();

    for (int kt = 0; kt < KT1; kt++) {
        cp_wait<1>();
        __syncthreads();
        int nxt = kt + 2;
        if (nxt < KT1) g1_load(sb, tok_s, nxt % 3, nxt * BK, e, n_base, tid);
        cp_commit();

        int sg = kt % 3;
#pragma unroll
        for (int ks = 0; ks < BK / 16; ks++) {
            int k16 = ks * 16;
            uint32_t a[2][4];
#pragma unroll
            for (int mf = 0; mf < 2; mf++)
                ldsm_x4(a[mf], sb + G1_A(sg) +
                        SWZ((wm * 32 + mf * 16 + lrow) * 128 + (k16 + lcol) * 2));
            uint32_t bg[2][4], bu[2][4];
#pragma unroll
            for (int ng = 0; ng < 2; ng++) {
                uint32_t sw = SWZ((k16 + lrow) * 128 + (wn * 32 + ng * 16 + lcol) * 2);
                ldsm_x4t(bg[ng], sb + G1_BG(sg) + sw);
                ldsm_x4t(bu[ng], sb + G1_BU(sg) + sw);
            }
#pragma unroll
            for (int mf = 0; mf < 2; mf++)
#pragma unroll
                for (int nf = 0; nf < 4; nf++) {
                    mma_f16(acc_g[mf][nf], a[mf], &bg[nf >> 1][(nf & 1) * 2]);
                    mma_f16(acc_u[mf][nf], a[mf], &bu[nf >> 1][(nf & 1) * 2]);
                }
        }
    }

    // epilogue: silu(g)*u -> fp16 -> g_hh
#pragma unroll
    for (int mf = 0; mf < 2; mf++) {
#pragma unroll
        for (int nf = 0; nf < 4; nf++) {
            int rl = wm * 32 + mf * 16 + r;
            int col = n_base + wn * 32 + nf * 8 + cq * 2;
            if (m_base + rl < cnt) {
                float g0 = acc_g[mf][nf][0], u0 = acc_u[mf][nf][0];
                float g1 = acc_g[mf][nf][1], u1 = acc_u[mf][nf][1];
                float v0 = (g0 / (1.f + __expf(-g0))) * u0;
                float v1 = (g1 / (1.f + __expf(-g1))) * u1;
                __half2* p = (__half2*)&g_hh[((size_t)e * TOK + m_base + rl) * ID + col];
                *p = __floats2half2_rn(v0, v1);
            }
            if (m_base + rl + 8 < cnt) {
                float g0 = acc_g[mf][nf][2], u0 = acc_u[mf][nf][2];
                float g1 = acc_g[mf][nf][3], u1 = acc_u[mf][nf][3];
                float v0 = (g0 / (1.f + __expf(-g0))) * u0;
                float v1 = (g1 / (1.f + __expf(-g1))) * u1;
                __half2* p = (__half2*)&g_hh[((size_t)e * TOK + m_base + rl + 8) * ID + col];
                *p = __floats2half2_rn(v0, v1);
            }
        }
    }
}

// ---------------- GEMM2: y = h @ Wd; 64x128x64, 3 CTAs/SM, swizzled, [n][k] B ---
#define G2_A(s)  ((s) * 8192)
#define G2_B(s)  (24576 + (s) * 16384)   // 128 n-rows x 128 B
#define G2_SMEM  73728

__device__ __forceinline__ void g2_load(uint32_t sb, int st, int k0,
                                        int e, int m_base, int n_base, int tid) {
    const __half* arow = g_hh + ((size_t)e * TOK + m_base) * ID + k0;
    const __half* brow = g_wdT + ((size_t)e * HD + n_base) * ID + k0;
#pragma unroll
    for (int i = 0; i < 4; i++) {                 // A: 512 chunks
        int idx = tid + i * NTHR;
        int row = idx >> 3, c = idx & 7;
        cp16(sb + G2_A(st) + SWZ(row * 128 + c * 16), arow + (size_t)row * ID + c * 8);
    }
#pragma unroll
    for (int i = 0; i < 8; i++) {                 // B: 128 n-rows x 8 chunks = 1024
        int idx = tid + i * NTHR;
        int row = idx >> 3, c = idx & 7;
        cp16(sb + G2_B(st) + SWZ(row * 128 + c * 16), brow + (size_t)row * ID + c * 8);
    }
}

__global__ void __launch_bounds__(NTHR, 3) gemm2_kernel() {
    extern __shared__ __align__(1024) char smem_raw[];
    uint32_t sb = saddr(smem_raw);

    int e = blockIdx.z;
    int cnt = g_cnt[e];
    int m_base = blockIdx.y * BM;
    if (m_base >= cnt) return;
    int n_base = blockIdx.x * BN2;
    int tid = threadIdx.x;

    int wid = tid >> 5, lane = tid & 31;
    int wm = wid >> 1, wn = wid & 1;               // 2 x 2 warps, warp 32x64
    int r = lane >> 2, cq = lane & 3;
    int lrow = lane & 15, lcol = (lane >> 4) << 3;
    // non-trans B on [n][k]: lanes 0-7 n-rows 0-7 k0, 8-15 rows 0-7 k+8,
    // 16-23 rows 8-15 k0, 24-31 rows 8-15 k+8
    int brow = (lane & 7) + ((lane >> 4) << 3);
    int bkof = ((lane >> 3) & 1) << 3;

    float acc[2][8][4];
#pragma unroll
    for (int mf = 0; mf < 2; mf++)
#pragma unroll
        for (int nf = 0; nf < 8; nf++)
#pragma unroll
            for (int k = 0; k < 4; k++) acc[mf][nf][k] = 0.f;

    g2_load(sb, 0, 0, e, m_base, n_base, tid);  cp_commit();
    g2_load(sb, 1, BK, e, m_base, n_base, tid); cp_commit();

    for (int kt = 0; kt < KT2; kt++) {
        cp_wait<1>();
        __syncthreads();
        int nxt = kt + 2;
        if (nxt < KT2) g2_load(sb, nxt % 3, nxt * BK, e, m_base, n_base, tid);
        cp_commit();

        int sg = kt % 3;
#pragma unroll
        for (int ks = 0; ks < BK / 16; ks++) {
            int k16 = ks * 16;
            uint32_t a[2][4];
#pragma unroll
            for (int mf = 0; mf < 2; mf++)
                ldsm_x4(a[mf], sb + G2_A(sg) +
                        SWZ((wm * 32 + mf * 16 + lrow) * 128 + (k16 + lcol) * 2));
            uint32_t b[4][4];
#pragma unroll
            for (int ng = 0; ng < 4; ng++)
                ldsm_x4(b[ng], sb + G2_B(sg) +
                        SWZ((wn * 64 + ng * 16 + brow) * 128 + (k16 + bkof) * 2));
#pragma unroll
            for (int mf = 0; mf < 2; mf++)
#pragma unroll
                for (int nf = 0; nf < 8; nf++)
                    mma_f16(acc[mf][nf], a[mf], &b[nf >> 1][(nf & 1) * 2]);
        }
    }

    // epilogue: plain stores to g_y[k][t]
#pragma unroll
    for (int mf = 0; mf < 2; mf++) {
        int rl0 = wm * 32 + mf * 16 + r;
        int pk0 = (m_base + rl0 < cnt) ? g_tokp[e * TOK + m_base + rl0] : -1;
        int pk1 = (m_base + rl0 + 8 < cnt) ? g_tokp[e * TOK + m_base + rl0 + 8] : -1;
#pragma unroll
        for (int nf = 0; nf < 8; nf++) {
            int col = n_base + wn * 64 + nf * 8 + cq * 2;
            if (pk0 != -1) {
                int t = pk0 & 0x7fffffff;
                int k = (uint32_t)pk0 >> 31;
                float2* p = (float2*)&g_y[((size_t)k * TOK + t) * HD + col];
                *p = make_float2(acc[mf][nf][0], acc[mf][nf][1]);
            }
            if (pk1 != -1) {
                int t = pk1 & 0x7fffffff;
                int k = (uint32_t)pk1 >> 31;
                float2* p = (float2*)&g_y[((size_t)k * TOK + t) * HD + col];
                *p = make_float2(acc[mf][nf][2], acc[mf][nf][3]);
            }
        }
    }
}

// ---------------- combine: out = w0*y0 + w1*y1 ----------------------------------
__global__ void combine_kernel(float4* __restrict__ out) {
    const int n4 = TOK * HD / 4;
    const float4* y0 = (const float4*)g_y;
    const float4* y1 = y0 + n4;
    for (int i = blockIdx.x * blockDim.x + threadIdx.x; i < n4; i += gridDim.x * blockDim.x) {
        int t = i / (HD / 4);
        float w0 = g_w2[2 * t], w1 = g_w2[2 * t + 1];
        float4 a = y0[i], b = y1[i];
        float4 o;
        o.x = w0 * a.x + w1 * b.x;
        o.y = w0 * a.y + w1 * b.y;
        o.z = w0 * a.z + w1 * b.z;
        o.w = w0 * a.w + w1 * b.w;
        out[i] = o;
    }
}

// ---------------- host launcher -------------------------------------------------
extern "C" void kernel_launch(void* const* d_in, const int* in_sizes, int n_in,
                              void* d_out, int out_size) {
    const float* x  = (const float*)d_in[0];
    const float* gw = (const float*)d_in[1];
    const float* wg = (const float*)d_in[2];
    const float* wu = (const float*)d_in[3];
    const float* wd = (const float*)d_in[4];
    (void)in_sizes; (void)n_in; (void)out_size;

    {
        dim3 grid(1024, 1, 2);
        conv_half_kernel<<<grid, 256>>>((const float4*)wg, (const float4*)wu);
    }
    {
        dim3 grid(HD / 32, ID / 32, NE);   // 64 x 44 x 8
        dim3 blk(32, 8, 1);
        convT_wd_kernel<<<grid, blk>>>(wd);
    }

    cudaFuncSetAttribute(router_kernel, cudaFuncAttributeMaxDynamicSharedMemorySize,
                         NE * HD * (int)sizeof(float));
    router_kernel<<<TOK * 32 / 256, 256, NE * HD * sizeof(float)>>>(x, gw);

    cudaFuncSetAttribute(gemm1_kernel, cudaFuncAttributeMaxDynamicSharedMemorySize, G1_SMEM);
    dim3 grid1(ID / BN1, TOK / BM, NE);     // 22 x 128 x 8
    gemm1_kernel<<<grid1, NTHR, G1_SMEM>>>();

    cudaFuncSetAttribute(gemm2_kernel, cudaFuncAttributeMaxDynamicSharedMemorySize, G2_SMEM);
    dim3 grid2(HD / BN2, TOK / BM, NE);     // 16 x 128 x 8
    gemm2_kernel<<<grid2, NTHR, G2_SMEM>>>();

    combine_kernel<<<2048, 256>>>((float4*)d_out);
}

// round 15
// speedup vs baseline: 1.1276x; 1.0159x over previous
#include <cuda_runtime.h>
#include <cuda_fp16.h>
#include <cstdint>

#define TOK 8192
#define HD  2048
#define ID  1408
#define NE  8

#define BM   64
#define BK   64
#define BN1  64
#define BN2  128
#define NTHR 128
#define KT1  (HD / BK)    // 32
#define KT2  (ID / BK)    // 22

// swizzle for 128B rows, 16B units
#define SWZ(b) ((uint32_t)(b) ^ (((uint32_t)(b) >> 3) & 0x70u))

// ---------------- device scratch (no allocations allowed) ----------------------
__device__ __half g_xh[(size_t)TOK * HD];       // fp16 x
__device__ __half g_wgh[(size_t)NE * HD * ID];  // fp16 weights, native [k][n]
__device__ __half g_wuh[(size_t)NE * HD * ID];
__device__ __half g_wdT[(size_t)NE * HD * ID];  // fp16 wd TRANSPOSED [e][H][I] ([n][k])
__device__ int    g_cnt[NE];
__device__ int    g_tokp[NE * TOK];             // token | (k<<31)
__device__ float  g_w2[TOK * 2];                // per-token (w0, w1)
__device__ __half g_hh[(size_t)NE * TOK * ID];  // fp16 intermediate (slot-indexed)
__device__ __half g_y[(size_t)2 * TOK * HD];    // unweighted expert outputs per k (fp16)

// ---------------- helpers ------------------------------------------------------
__device__ __forceinline__ uint32_t saddr(const void* p) {
    return (uint32_t)__cvta_generic_to_shared(p);
}
__device__ __forceinline__ void cp16(uint32_t dst, const void* src) {
    asm volatile("cp.async.cg.shared.global [%0], [%1], 16;" :: "r"(dst), "l"(src));
}
__device__ __forceinline__ void cp_commit() { asm volatile("cp.async.commit_group;"); }
template <int N>
__device__ __forceinline__ void cp_wait() { asm volatile("cp.async.wait_group %0;" :: "n"(N)); }

__device__ __forceinline__ void ldsm_x4(uint32_t* r, uint32_t addr) {
    asm volatile("ldmatrix.sync.aligned.m8n8.x4.shared.b16 {%0,%1,%2,%3}, [%4];"
                 : "=r"(r[0]), "=r"(r[1]), "=r"(r[2]), "=r"(r[3]) : "r"(addr));
}
__device__ __forceinline__ void ldsm_x4t(uint32_t* r, uint32_t addr) {
    asm volatile("ldmatrix.sync.aligned.m8n8.x4.trans.shared.b16 {%0,%1,%2,%3}, [%4];"
                 : "=r"(r[0]), "=r"(r[1]), "=r"(r[2]), "=r"(r[3]) : "r"(addr));
}
__device__ __forceinline__ void mma_f16(float d[4], const uint32_t a[4], const uint32_t b[2]) {
    asm volatile(
        "mma.sync.aligned.m16n8k16.row.col.f32.f16.f16.f32 "
        "{%0,%1,%2,%3}, {%4,%5,%6,%7}, {%8,%9}, {%0,%1,%2,%3};"
        : "+f"(d[0]), "+f"(d[1]), "+f"(d[2]), "+f"(d[3])
        : "r"(a[0]), "r"(a[1]), "r"(a[2]), "r"(a[3]), "r"(b[0]), "r"(b[1]));
}

// ---------------- fused prologue: wg/wu conv + wd transpose + cnt zero ----------
// grid.z: 0 -> wg conv, 1 -> wu conv, 2+e -> wdT transpose for expert e.
// flat 256-thread blocks; transposes re-derive (tx, ty) from tid.
__global__ void prologue_kernel(const float4* __restrict__ wg,
                                const float4* __restrict__ wu,
                                const float*  __restrict__ wd) {
    int z = blockIdx.z;
    if (z < 2) {
        if (z == 0 && blockIdx.x == 0 && threadIdx.x < NE) g_cnt[threadIdx.x] = 0;
        const int n4 = NE * HD * ID / 4;
        const float4* in = z == 0 ? wg : wu;
        uint2* out = (uint2*)(z == 0 ? g_wgh : g_wuh);
        for (int i = blockIdx.x * blockDim.x + threadIdx.x; i < n4;
             i += gridDim.x * blockDim.x) {
            float4 v = in[i];
            __half2 lo = __floats2half2_rn(v.x, v.y);
            __half2 hi = __floats2half2_rn(v.z, v.w);
            uint2 o;
            o.x = *(uint32_t*)&lo;
            o.y = *(uint32_t*)&hi;
            out[i] = o;
        }
    } else {
        // wd [I][H] fp32 -> wdT [H][I] fp16, 32x32 tile transpose
        __shared__ float t[32][33];
        int e = z - 2;
        const float* in = wd + (size_t)e * ID * HD;
        __half* out = g_wdT + (size_t)e * HD * ID;
        const int nbx = HD / 32;                     // 64
        for (int b = blockIdx.x; b < (HD / 32) * (ID / 32); b += gridDim.x) {
            int c0 = (b % nbx) * 32;                 // HD dim
            int r0 = (b / nbx) * 32;                 // ID dim
            int tx = threadIdx.x & 31, ty = threadIdx.x >> 5;
            __syncthreads();
#pragma unroll
            for (int i = 0; i < 4; i++)
                t[ty + i * 8][tx] = in[(size_t)(r0 + ty + i * 8) * HD + c0 + tx];
            __syncthreads();
#pragma unroll
            for (int i = 0; i < 4; i++)
                out[(size_t)(c0 + ty + i * 8) * ID + r0 + tx] =
                    __float2half_rn(t[tx][ty + i * 8]);
        }
    }
}

// Router + fused fp16 conversion of x. One warp per token.
__global__ void router_kernel(const float* __restrict__ x, const float* __restrict__ gw) {
    extern __shared__ float s_gw[];  // NE*HD = 64 KB
    for (int i = threadIdx.x; i < NE * HD; i += blockDim.x) s_gw[i] = gw[i];
    __syncthreads();

    int gtid = blockIdx.x * blockDim.x + threadIdx.x;
    int t = gtid >> 5, lane = gtid & 31;
    if (t >= TOK) return;

    float acc[NE];
#pragma unroll
    for (int e = 0; e < NE; e++) acc[e] = 0.f;

    const float* xr = x + (size_t)t * HD;
    __half* xo = g_xh + (size_t)t * HD;
    for (int i = lane; i < HD; i += 32) {
        float xv = xr[i];
        xo[i] = __float2half_rn(xv);
#pragma unroll
        for (int e = 0; e < NE; e++) acc[e] += xv * s_gw[e * HD + i];
    }
#pragma unroll
    for (int e = 0; e < NE; e++) {
#pragma unroll
        for (int off = 16; off > 0; off >>= 1)
            acc[e] += __shfl_xor_sync(0xffffffffu, acc[e], off);
    }
    if (lane == 0) {
        int i0 = 0; float l0 = acc[0];
#pragma unroll
        for (int e = 1; e < NE; e++) if (acc[e] > l0) { l0 = acc[e]; i0 = e; }
        int i1 = -1; float l1 = -1e30f;
#pragma unroll
        for (int e = 0; e < NE; e++) if (e != i0 && acc[e] > l1) { l1 = acc[e]; i1 = e; }
        float ex = __expf(l1 - l0);
        float w0 = 1.f / (1.f + ex);
        float w1 = ex * w0;
        g_w2[2 * t] = w0;
        g_w2[2 * t + 1] = w1;
        int s0 = atomicAdd(&g_cnt[i0], 1);
        g_tokp[i0 * TOK + s0] = t;                          // k = 0
        int s1 = atomicAdd(&g_cnt[i1], 1);
        g_tokp[i1 * TOK + s1] = t | 0x80000000;             // k = 1
    }
}

// ---------------- GEMM1: h = silu(x@Wg)*(x@Wu); 64x64x64, 3 CTAs/SM, swizzled ---
#define G1_A(s)  ((s) * 8192)
#define G1_BG(s) (24576 + (s) * 8192)
#define G1_BU(s) (49152 + (s) * 8192)
#define G1_TOK   73728
#define G1_SMEM  73984

__device__ __forceinline__ void g1_load(uint32_t sb, const int* tok_s, int st, int k0,
                                        int e, int n_base, int tid) {
#pragma unroll
    for (int i = 0; i < 4; i++) {                 // A: 64 rows x 8 chunks = 512
        int idx = tid + i * NTHR;
        int row = idx >> 3, c = idx & 7;
        cp16(sb + G1_A(st) + SWZ(row * 128 + c * 16),
             &g_xh[(size_t)tok_s[row] * HD + k0 + c * 8]);
    }
    const __half* bg = g_wgh + ((size_t)e * HD + k0) * ID + n_base;
    const __half* bu = g_wuh + ((size_t)e * HD + k0) * ID + n_base;
#pragma unroll
    for (int i = 0; i < 4; i++) {                 // Bg/Bu: 64 k-rows x 8 chunks
        int idx = tid + i * NTHR;
        int kr = idx >> 3, c = idx & 7;
        uint32_t sw = SWZ(kr * 128 + c * 16);
        cp16(sb + G1_BG(st) + sw, bg + (size_t)kr * ID + c * 8);
        cp16(sb + G1_BU(st) + sw, bu + (size_t)kr * ID + c * 8);
    }
}

__global__ void __launch_bounds__(NTHR, 3) gemm1_kernel() {
    extern __shared__ __align__(1024) char smem_raw[];
    uint32_t sb = saddr(smem_raw);
    int* tok_s = (int*)(smem_raw + G1_TOK);

    int e = blockIdx.z;
    int cnt = g_cnt[e];
    int m_base = blockIdx.y * BM;
    if (m_base >= cnt) return;
    int n_base = blockIdx.x * BN1;
    int tid = threadIdx.x;

    if (tid < BM) {
        int m = m_base + tid;
        tok_s[tid] = (m < cnt) ? (g_tokp[e * TOK + m] & 0x7fffffff) : 0;
    }
    __syncthreads();

    int wid = tid >> 5, lane = tid & 31;
    int wm = wid >> 1, wn = wid & 1;               // 2 x 2 warps, warp 32x32
    int r = lane >> 2, cq = lane & 3;
    int lrow = lane & 15, lcol = (lane >> 4) << 3;

    float acc_g[2][4][4], acc_u[2][4][4];
#pragma unroll
    for (int mf = 0; mf < 2; mf++)
#pragma unroll
        for (int nf = 0; nf < 4; nf++)
#pragma unroll
            for (int k = 0; k < 4; k++) { acc_g[mf][nf][k] = 0.f; acc_u[mf][nf][k] = 0.f; }

    g1_load(sb, tok_s, 0, 0, e, n_base, tid);  cp_commit();
    g1_load(sb, tok_s, 1, BK, e, n_base, tid); cp_commit();

    for (int kt = 0; kt < KT1; kt++) {
        cp_wait<1>();
        __syncthreads();
        int nxt = kt + 2;
        if (nxt < KT1) g1_load(sb, tok_s, nxt % 3, nxt * BK, e, n_base, tid);
        cp_commit();

        int sg = kt % 3;
#pragma unroll
        for (int ks = 0; ks < BK / 16; ks++) {
            int k16 = ks * 16;
            uint32_t a[2][4];
#pragma unroll
            for (int mf = 0; mf < 2; mf++)
                ldsm_x4(a[mf], sb + G1_A(sg) +
                        SWZ((wm * 32 + mf * 16 + lrow) * 128 + (k16 + lcol) * 2));
            uint32_t bg[2][4], bu[2][4];
#pragma unroll
            for (int ng = 0; ng < 2; ng++) {
                uint32_t sw = SWZ((k16 + lrow) * 128 + (wn * 32 + ng * 16 + lcol) * 2);
                ldsm_x4t(bg[ng], sb + G1_BG(sg) + sw);
                ldsm_x4t(bu[ng], sb + G1_BU(sg) + sw);
            }
#pragma unroll
            for (int mf = 0; mf < 2; mf++)
#pragma unroll
                for (int nf = 0; nf < 4; nf++) {
                    mma_f16(acc_g[mf][nf], a[mf], &bg[nf >> 1][(nf & 1) * 2]);
                    mma_f16(acc_u[mf][nf], a[mf], &bu[nf >> 1][(nf & 1) * 2]);
                }
        }
    }

    // epilogue: silu(g)*u -> fp16 -> g_hh
#pragma unroll
    for (int mf = 0; mf < 2; mf++) {
#pragma unroll
        for (int nf = 0; nf < 4; nf++) {
            int rl = wm * 32 + mf * 16 + r;
            int col = n_base + wn * 32 + nf * 8 + cq * 2;
            if (m_base + rl < cnt) {
                float g0 = acc_g[mf][nf][0], u0 = acc_u[mf][nf][0];
                float g1 = acc_g[mf][nf][1], u1 = acc_u[mf][nf][1];
                float v0 = (g0 / (1.f + __expf(-g0))) * u0;
                float v1 = (g1 / (1.f + __expf(-g1))) * u1;
                __half2* p = (__half2*)&g_hh[((size_t)e * TOK + m_base + rl) * ID + col];
                *p = __floats2half2_rn(v0, v1);
            }
            if (m_base + rl + 8 < cnt) {
                float g0 = acc_g[mf][nf][2], u0 = acc_u[mf][nf][2];
                float g1 = acc_g[mf][nf][3], u1 = acc_u[mf][nf][3];
                float v0 = (g0 / (1.f + __expf(-g0))) * u0;
                float v1 = (g1 / (1.f + __expf(-g1))) * u1;
                __half2* p = (__half2*)&g_hh[((size_t)e * TOK + m_base + rl + 8) * ID + col];
                *p = __floats2half2_rn(v0, v1);
            }
        }
    }
}

// ---------------- GEMM2: y = h @ Wd; 64x128x64, 3 CTAs/SM, swizzled, [n][k] B ---
#define G2_A(s)  ((s) * 8192)
#define G2_B(s)  (24576 + (s) * 16384)   // 128 n-rows x 128 B
#define G2_SMEM  73728

__device__ __forceinline__ void g2_load(uint32_t sb, int st, int k0,
                                        int e, int m_base, int n_base, int tid) {
    const __half* arow = g_hh + ((size_t)e * TOK + m_base) * ID + k0;
    const __half* brow = g_wdT + ((size_t)e * HD + n_base) * ID + k0;
#pragma unroll
    for (int i = 0; i < 4; i++) {                 // A: 512 chunks
        int idx = tid + i * NTHR;
        int row = idx >> 3, c = idx & 7;
        cp16(sb + G2_A(st) + SWZ(row * 128 + c * 16), arow + (size_t)row * ID + c * 8);
    }
#pragma unroll
    for (int i = 0; i < 8; i++) {                 // B: 128 n-rows x 8 chunks = 1024
        int idx = tid + i * NTHR;
        int row = idx >> 3, c = idx & 7;
        cp16(sb + G2_B(st) + SWZ(row * 128 + c * 16), brow + (size_t)row * ID + c * 8);
    }
}

__global__ void __launch_bounds__(NTHR, 3) gemm2_kernel() {
    extern __shared__ __align__(1024) char smem_raw[];
    uint32_t sb = saddr(smem_raw);

    int e = blockIdx.z;
    int cnt = g_cnt[e];
    int m_base = blockIdx.y * BM;
    if (m_base >= cnt) return;
    int n_base = blockIdx.x * BN2;
    int tid = threadIdx.x;

    int wid = tid >> 5, lane = tid & 31;
    int wm = wid >> 1, wn = wid & 1;               // 2 x 2 warps, warp 32x64
    int r = lane >> 2, cq = lane & 3;
    int lrow = lane & 15, lcol = (lane >> 4) << 3;
    // non-trans B on [n][k]: lanes 0-7 n-rows 0-7 k0, 8-15 rows 0-7 k+8,
    // 16-23 rows 8-15 k0, 24-31 rows 8-15 k+8
    int brow = (lane & 7) + ((lane >> 4) << 3);
    int bkof = ((lane >> 3) & 1) << 3;

    float acc[2][8][4];
#pragma unroll
    for (int mf = 0; mf < 2; mf++)
#pragma unroll
        for (int nf = 0; nf < 8; nf++)
#pragma unroll
            for (int k = 0; k < 4; k++) acc[mf][nf][k] = 0.f;

    g2_load(sb, 0, 0, e, m_base, n_base, tid);  cp_commit();
    g2_load(sb, 1, BK, e, m_base, n_base, tid); cp_commit();

    for (int kt = 0; kt < KT2; kt++) {
        cp_wait<1>();
        __syncthreads();
        int nxt = kt + 2;
        if (nxt < KT2) g2_load(sb, nxt % 3, nxt * BK, e, m_base, n_base, tid);
        cp_commit();

        int sg = kt % 3;
#pragma unroll
        for (int ks = 0; ks < BK / 16; ks++) {
            int k16 = ks * 16;
            uint32_t a[2][4];
#pragma unroll
            for (int mf = 0; mf < 2; mf++)
                ldsm_x4(a[mf], sb + G2_A(sg) +
                        SWZ((wm * 32 + mf * 16 + lrow) * 128 + (k16 + lcol) * 2));
            uint32_t b[4][4];
#pragma unroll
            for (int ng = 0; ng < 4; ng++)
                ldsm_x4(b[ng], sb + G2_B(sg) +
                        SWZ((wn * 64 + ng * 16 + brow) * 128 + (k16 + bkof) * 2));
#pragma unroll
            for (int mf = 0; mf < 2; mf++)
#pragma unroll
                for (int nf = 0; nf < 8; nf++)
                    mma_f16(acc[mf][nf], a[mf], &b[nf >> 1][(nf & 1) * 2]);
        }
    }

    // epilogue: fp16 stores to g_y[k][t]
#pragma unroll
    for (int mf = 0; mf < 2; mf++) {
        int rl0 = wm * 32 + mf * 16 + r;
        int pk0 = (m_base + rl0 < cnt) ? g_tokp[e * TOK + m_base + rl0] : -1;
        int pk1 = (m_base + rl0 + 8 < cnt) ? g_tokp[e * TOK + m_base + rl0 + 8] : -1;
#pragma unroll
        for (int nf = 0; nf < 8; nf++) {
            int col = n_base + wn * 64 + nf * 8 + cq * 2;
            if (pk0 != -1) {
                int t = pk0 & 0x7fffffff;
                int k = (uint32_t)pk0 >> 31;
                __half2* p = (__half2*)&g_y[((size_t)k * TOK + t) * HD + col];
                *p = __floats2half2_rn(acc[mf][nf][0], acc[mf][nf][1]);
            }
            if (pk1 != -1) {
                int t = pk1 & 0x7fffffff;
                int k = (uint32_t)pk1 >> 31;
                __half2* p = (__half2*)&g_y[((size_t)k * TOK + t) * HD + col];
                *p = __floats2half2_rn(acc[mf][nf][2], acc[mf][nf][3]);
            }
        }
    }
}

// ---------------- combine: out = w0*y0 + w1*y1 (y in fp16) ----------------------
__global__ void combine_kernel(float4* __restrict__ out) {
    const int n4 = TOK * HD / 4;
    const uint2* y0 = (const uint2*)g_y;                 // 4 halves per uint2
    const uint2* y1 = y0 + n4;
    for (int i = blockIdx.x * blockDim.x + threadIdx.x; i < n4; i += gridDim.x * blockDim.x) {
        int t = i / (HD / 4);
        float w0 = g_w2[2 * t], w1 = g_w2[2 * t + 1];
        uint2 a = y0[i], b = y1[i];
        float2 a0 = __half22float2(*(__half2*)&a.x);
        float2 a1 = __half22float2(*(__half2*)&a.y);
        float2 b0 = __half22float2(*(__half2*)&b.x);
        float2 b1 = __half22float2(*(__half2*)&b.y);
        float4 o;
        o.x = w0 * a0.x + w1 * b0.x;
        o.y = w0 * a0.y + w1 * b0.y;
        o.z = w0 * a1.x + w1 * b1.x;
        o.w = w0 * a1.y + w1 * b1.y;
        out[i] = o;
    }
}

// ---------------- host launcher -------------------------------------------------
extern "C" void kernel_launch(void* const* d_in, const int* in_sizes, int n_in,
                              void* d_out, int out_size) {
    const float* x  = (const float*)d_in[0];
    const float* gw = (const float*)d_in[1];
    const float* wg = (const float*)d_in[2];
    const float* wu = (const float*)d_in[3];
    const float* wd = (const float*)d_in[4];
    (void)in_sizes; (void)n_in; (void)out_size;

    {
        dim3 grid(512, 1, 2 + NE);   // z=0,1: wg/wu conv; z=2..9: wdT per expert
        prologue_kernel<<<grid, 256>>>((const float4*)wg, (const float4*)wu, wd);
    }

    cudaFuncSetAttribute(router_kernel, cudaFuncAttributeMaxDynamicSharedMemorySize,
                         NE * HD * (int)sizeof(float));
    router_kernel<<<TOK * 32 / 256, 256, NE * HD * sizeof(float)>>>(x, gw);

    cudaFuncSetAttribute(gemm1_kernel, cudaFuncAttributeMaxDynamicSharedMemorySize, G1_SMEM);
    dim3 grid1(ID / BN1, TOK / BM, NE);     // 22 x 128 x 8
    gemm1_kernel<<<grid1, NTHR, G1_SMEM>>>();

    cudaFuncSetAttribute(gemm2_kernel, cudaFuncAttributeMaxDynamicSharedMemorySize, G2_SMEM);
    dim3 grid2(HD / BN2, TOK / BM, NE);     // 16 x 128 x 8
    gemm2_kernel<<<grid2, NTHR, G2_SMEM>>>();

    combine_kernel<<<2048, 256>>>((float4*)d_out);
}